// round 13
// baseline (speedup 1.0000x reference)
#include <cuda_runtime.h>
#include <cstdint>

#define D_DIM 256
#define D4    64          // D in float4
#define BM    128         // rows per block
#define BN    256         // codes per k-tile
#define BK    8           // d-chunk for Bs double buffer
#define TM    8
#define TN    8
#define NTHREADS 512

typedef unsigned long long u64;

// packed dual-FMA: d = a*b + d, lane-wise fp32 (identical rounding to fmaf)
__device__ __forceinline__ void ffma2(u64& d, u64 a, u64 b) {
    asm("fma.rn.f32x2 %0, %1, %2, %0;" : "+l"(d) : "l"(a), "l"(b));
}
__device__ __forceinline__ u64 ffma2_3(u64 a, u64 b, u64 c) {
    u64 d;
    asm("fma.rn.f32x2 %0, %1, %2, %3;" : "=l"(d) : "l"(a), "l"(b), "l"(c));
    return d;
}
__device__ __forceinline__ u64 pack2(float x) {
    u64 d;
    asm("mov.b64 %0, {%1, %1};" : "=l"(d) : "f"(x));
    return d;
}
__device__ __forceinline__ void unpack2(u64 v, float& lo, float& hi) {
    asm("mov.b64 {%0, %1}, %2;" : "=f"(lo), "=f"(hi) : "l"(v));
}

// ---------------------------------------------------------------------------
// vq_kernel: fused distances + running argmin + gather, emulating the
// reference's fp32 numerics (verified exact R8/R10/R12):
//   score_k = fl( xsq_r - 2*dot(x_r, w_k) )
//   dot/xsq = single fp32 FMA chain, d ascending;  argmin = first index ties
//
// FFMA2 layout: accumulators packed along row pairs.
//   warp grid 4x4: wm = wid>>2, wn = wid&3; lane: mg = lane>>3, ng = lane&7
//   rows  wm*32 + mg*4 + {0..3} and +16  (A frags = natural f32x2 row pairs)
//   cols  wn*64 + ng*4 + {0..3} and +32  (B in smem pre-duplicated (w,w))
//
//   As  [D_DIM][BM] float  persistent X tile (transposed), 128 KB
//   Bs2 [2][BK][BN] u64    double-buffered duplicated W chunks, 32 KB
//   Xsq [BM] float
// ---------------------------------------------------------------------------
__global__ __launch_bounds__(NTHREADS, 1)
void vq_kernel(const float* __restrict__ X, const float* __restrict__ W,
               float* __restrict__ outq, float* __restrict__ outidx,
               int Kn, int write_idx)
{
    extern __shared__ float smem[];
    float* As  = smem;                                   // [D_DIM][BM]
    u64*   Bs2 = (u64*)(smem + D_DIM * BM);              // [2][BK][BN]
    float* Xsq = (float*)(Bs2 + 2 * BK * BN);            // [BM]
    // overlay (valid only after last GEMM __syncthreads):
    float* redv = (float*)Bs2;                           // [BM*4]
    int*   redk = (int*)(redv + BM * 4);                 // [BM*4]

    const int tid  = threadIdx.x;
    const int lane = tid & 31;
    const int wid  = tid >> 5;
    const int wm   = wid >> 2;
    const int wn   = wid & 3;
    const int mg   = lane >> 3;
    const int ng   = lane & 7;
    const int row0 = blockIdx.x * BM;

    const int rowA0 = wm * 32 + mg * 4;
    const int rowA1 = rowA0 + 16;
    const int colB0 = wn * 64 + ng * 4;
    const int colB1 = colB0 + 32;

    const float4* X4 = (const float4*)X;
    const float4* W4 = (const float4*)W;

    // --- load X tile transposed into As (one-time; conflict-free stores) ---
    for (int i = tid; i < BM * D4; i += NTHREADS) {
        int r  = i & (BM - 1);
        int d4 = i >> 7;
        float4 v = X4[(size_t)(row0 + r) * D4 + d4];
        As[(d4 * 4 + 0) * BM + r] = v.x;
        As[(d4 * 4 + 1) * BM + r] = v.y;
        As[(d4 * 4 + 2) * BM + r] = v.z;
        As[(d4 * 4 + 3) * BM + r] = v.w;
    }
    __syncthreads();

    // --- xsq: exact sequential fp32 fma chain over d ascending ---
    if (tid < BM) {
        float a = 0.f;
        #pragma unroll 8
        for (int d = 0; d < D_DIM; d++) {
            float v = As[d * BM + tid];
            a = fmaf(v, v, a);
        }
        Xsq[tid] = a;
    }
    __syncthreads();

    // xr packed as row pairs (Xsq rows contiguous, 16B aligned)
    u64 xr2[4];
    {
        ulonglong2 x0 = *(const ulonglong2*)&Xsq[rowA0];
        ulonglong2 x1 = *(const ulonglong2*)&Xsq[rowA1];
        xr2[0] = x0.x; xr2[1] = x0.y; xr2[2] = x1.x; xr2[3] = x1.y;
    }

    float bestv[TM];
    int   bestk[TM];
    #pragma unroll
    for (int i = 0; i < TM; i++) { bestv[i] = 3.402823e38f; bestk[i] = 0; }

    // Bs2 loader: thread (lk = tid&255, lhalf = tid>>8) loads one float4 of
    // W row lk covering d = dc*8 + lhalf*4 + {0..3}; stores duplicated pairs.
    const int lk    = tid & 255;
    const int lhalf = tid >> 8;

    const u64 NEG2 = 0xC0000000C0000000ULL;   // (-2.0f, -2.0f)

    const int nkt = Kn / BN;
    for (int kt = 0; kt < nkt; kt++) {
        const int kbase = kt * BN;

        u64 acc2[4][TN];
        #pragma unroll
        for (int ip = 0; ip < 4; ip++)
            #pragma unroll
            for (int j = 0; j < TN; j++) acc2[ip][j] = 0ULL;

        // prologue: chunk 0 -> buffer 0
        float4 s = W4[(size_t)(kbase + lk) * D4 + lhalf];
        {
            u64* B = Bs2 + (lhalf * 4) * BN + lk;
            B[0 * BN] = pack2(s.x);
            B[1 * BN] = pack2(s.y);
            B[2 * BN] = pack2(s.z);
            B[3 * BN] = pack2(s.w);
        }
        __syncthreads();

        #pragma unroll 1
        for (int dc = 0; dc < D_DIM / BK; dc++) {
            // issue global load for next chunk early (L2-resident)
            if (dc < D_DIM / BK - 1) {
                s = W4[(size_t)(kbase + lk) * D4 + (dc + 1) * 2 + lhalf];
            }
            const float* A  = As + dc * BK * BM;
            const u64*   Bd = Bs2 + (dc & 1) * (BK * BN);
            #pragma unroll
            for (int dd = 0; dd < BK; dd++) {
                // A rows as natural pairs: (r0,r1),(r2,r3) per LDS.128
                ulonglong2 a01 = *(const ulonglong2*)&A[dd * BM + rowA0];
                ulonglong2 a23 = *(const ulonglong2*)&A[dd * BM + rowA1];
                const u64* Br  = Bd + dd * BN;
                ulonglong2 q0  = *(const ulonglong2*)&Br[colB0];
                ulonglong2 q1  = *(const ulonglong2*)&Br[colB0 + 2];
                ulonglong2 q2  = *(const ulonglong2*)&Br[colB1];
                ulonglong2 q3  = *(const ulonglong2*)&Br[colB1 + 2];
                u64 aa[4] = {a01.x, a01.y, a23.x, a23.y};
                u64 bb[8] = {q0.x, q0.y, q1.x, q1.y, q2.x, q2.y, q3.x, q3.y};
                #pragma unroll
                for (int ip = 0; ip < 4; ip++)
                    #pragma unroll
                    for (int j = 0; j < TN; j++)
                        ffma2(acc2[ip][j], aa[ip], bb[j]);
            }
            if (dc < D_DIM / BK - 1) {
                u64* Bw = Bs2 + ((dc + 1) & 1) * (BK * BN) + (lhalf * 4) * BN + lk;
                Bw[0 * BN] = pack2(s.x);
                Bw[1 * BN] = pack2(s.y);
                Bw[2 * BN] = pack2(s.z);
                Bw[3 * BN] = pack2(s.w);
            }
            __syncthreads();
        }

        // epilogue: sc2 = fl(xsq - 2*acc) packed; ascending k, strict < ties
        #pragma unroll
        for (int j = 0; j < TN; j++) {
            const int kk = kbase + (j < 4 ? colB0 + j : colB1 + j - 4);
            #pragma unroll
            for (int ip = 0; ip < 4; ip++) {
                u64 sc2 = ffma2_3(acc2[ip][j], NEG2, xr2[ip]);
                float lo, hi;
                unpack2(sc2, lo, hi);
                const int i0 = ip * 2, i1 = i0 + 1;
                if (lo < bestv[i0]) { bestv[i0] = lo; bestk[i0] = kk; }
                if (hi < bestv[i1]) { bestv[i1] = hi; bestk[i1] = kk; }
            }
        }
    }
    // (last dc iteration ended with __syncthreads: all GEMM smem reads done)

    // rows handled by this thread, in bestv index order i=0..7:
    //   i=0..3 -> rowA0 + {0,1,2,3}?  NO: pairs are (rowA0+0,rowA0+1),(rowA0+2,rowA0+3),
    //   (rowA1+0,rowA1+1),(rowA1+2,rowA1+3) => i -> (i<4 ? rowA0+i : rowA1+i-4). Same as R12.

    // --- step 1: butterfly reduce over the 8 ng-lanes sharing each row ---
    #pragma unroll
    for (int i = 0; i < TM; i++) {
        float v = bestv[i];
        int   b = bestk[i];
        #pragma unroll
        for (int o = 1; o <= 4; o <<= 1) {
            float v2 = __shfl_xor_sync(0xffffffffu, v, o);
            int   b2 = __shfl_xor_sync(0xffffffffu, b, o);
            if (v2 < v || (v2 == v && b2 < b)) { v = v2; b = b2; }
        }
        if (ng == 0) {
            const int rloc = (i < 4 ? rowA0 + i : rowA1 + i - 4);
            redv[rloc * 4 + wn] = v;
            redk[rloc * 4 + wn] = b;
        }
    }
    __syncthreads();

    // --- step 2: combine the 4 wn-partials per row; gather in teams of 4 ---
    {
        const int r    = tid >> 2;   // 0..127
        const int team = tid & 3;
        float v = redv[r * 4 + 0];
        int   b = redk[r * 4 + 0];
        #pragma unroll
        for (int t = 1; t < 4; t++) {
            float v2 = redv[r * 4 + t];
            int   b2 = redk[r * 4 + t];
            if (v2 < v || (v2 == v && b2 < b)) { v = v2; b = b2; }
        }
        const int row = row0 + r;
        if (write_idx && team == 0) outidx[row] = (float)b;
        const float4* src = W4 + (size_t)b * D4;
        float4*       dst = (float4*)outq + (size_t)row * D4;
        #pragma unroll
        for (int c = 0; c < 16; c++) dst[c * 4 + team] = src[c * 4 + team];
    }
}

// ---------------------------------------------------------------------------
extern "C" void kernel_launch(void* const* d_in, const int* in_sizes, int n_in,
                              void* d_out, int out_size) {
    (void)n_in;
    const float* X = (const float*)d_in[0];
    const float* W = (const float*)d_in[1];
    int nx = in_sizes[0], nw = in_sizes[1];
    if (nx < nw) {
        const float* t = X; X = W; W = t;
        int tt = nx; nx = nw; nw = tt;
    }
    const int Nrows = nx / D_DIM;   // 32768
    const int Kn    = nw / D_DIM;   // 8192

    float* outq = (float*)d_out;
    const int write_idx = (out_size >= Nrows * D_DIM + Nrows) ? 1 : 0;
    float* outidx = write_idx ? ((float*)d_out + (size_t)Nrows * D_DIM) : nullptr;

    const size_t SMEM_BYTES =
        (size_t)D_DIM * BM * sizeof(float)        // As  131072
        + (size_t)2 * BK * BN * sizeof(u64)       // Bs2  32768
        + (size_t)BM * sizeof(float);             // Xsq    512
    cudaFuncSetAttribute(vq_kernel, cudaFuncAttributeMaxDynamicSharedMemorySize,
                         (int)SMEM_BYTES);

    vq_kernel<<<Nrows / BM, NTHREADS, SMEM_BYTES>>>(X, W, outq, outidx, Kn, write_idx);
}

// round 17
// speedup vs baseline: 1.5342x; 1.5342x over previous
#include <cuda_runtime.h>
#include <cstdint>

#define D_DIM 256
#define D4    64          // D in float4
#define BM    64          // rows per block (halved: 2 CTAs/SM)
#define BN    256         // codes per k-tile
#define BK    8           // d-chunk for Bs double buffer
#define TM    8
#define TN    8
#define NTHREADS 256

// ---------------------------------------------------------------------------
// vq_kernel: fused distances + running argmin + gather, emulating the
// reference's fp32 numerics (verified exact R8/R10/R12):
//   score_k = fl( xsq_r - 2*dot(x_r, w_k) )
//   dot/xsq = single fp32 FMA chain, d ascending;  argmin = first index ties
//
// 2-CTA/SM version: BM=64, 256 threads, 80.5 KB smem/CTA -> occupancy 2.
// Warp grid 2x4 over the 64x256 tile: wm = wid>>2 (0..1), wn = wid&3.
// Warp tile 32x64; lane: mg = lane>>3, ng = lane&7 (conflict-free frags):
//   A frag: rows wm*32 + mg*4 + {0..3} and +16   (2x LDS.128, 64B distinct)
//   B frag: cols wn*64 + ng*4 + {0..3} and +32   (2x LDS.128, 128B distinct)
//
//   As [D_DIM][BM]  persistent X tile (transposed), 64 KB
//   Bs [2][BK][BN]  double-buffered W chunks (transposed), 16 KB
//   Xsq[BM]; reduction scratch overlays Bs after the GEMM.
// ---------------------------------------------------------------------------
__global__ __launch_bounds__(NTHREADS, 2)
void vq_kernel(const float* __restrict__ X, const float* __restrict__ W,
               float* __restrict__ outq, float* __restrict__ outidx,
               int Kn, int write_idx)
{
    extern __shared__ float smem[];
    float* As  = smem;                            // [D_DIM][BM]
    float* Bs  = smem + D_DIM * BM;               // [2][BK][BN]
    float* Xsq = smem + D_DIM * BM + 2 * BK * BN; // [BM]
    // overlay (valid only after last GEMM __syncthreads):
    float* redv = Bs;                             // [BM*4]
    int*   redk = (int*)(Bs + BM * 4);            // [BM*4]

    const int tid  = threadIdx.x;
    const int lane = tid & 31;
    const int wid  = tid >> 5;
    const int wm   = wid >> 2;          // 0..1
    const int wn   = wid & 3;           // 0..3
    const int mg   = lane >> 3;         // 0..3
    const int ng   = lane & 7;          // 0..7
    const int row0 = blockIdx.x * BM;

    const int rowA0 = wm * 32 + mg * 4;
    const int rowA1 = rowA0 + 16;
    const int colB0 = wn * 64 + ng * 4;
    const int colB1 = colB0 + 32;

    const float4* X4 = (const float4*)X;
    const float4* W4 = (const float4*)W;

    // --- load X tile transposed into As (one-time; conflict-free stores) ---
    for (int i = tid; i < BM * D4; i += NTHREADS) {
        int r  = i & (BM - 1);
        int d4 = i >> 6;
        float4 v = X4[(size_t)(row0 + r) * D4 + d4];
        As[(d4 * 4 + 0) * BM + r] = v.x;
        As[(d4 * 4 + 1) * BM + r] = v.y;
        As[(d4 * 4 + 2) * BM + r] = v.z;
        As[(d4 * 4 + 3) * BM + r] = v.w;
    }
    __syncthreads();

    // --- xsq: exact sequential fp32 fma chain over d ascending ---
    if (tid < BM) {
        float a = 0.f;
        #pragma unroll 8
        for (int d = 0; d < D_DIM; d++) {
            float v = As[d * BM + tid];
            a = fmaf(v, v, a);
        }
        Xsq[tid] = a;
    }
    __syncthreads();

    float xr[TM];
    #pragma unroll
    for (int i = 0; i < TM; i++)
        xr[i] = Xsq[(i < 4 ? rowA0 + i : rowA1 + i - 4)];

    float bestv[TM];
    int   bestk[TM];
    #pragma unroll
    for (int i = 0; i < TM; i++) { bestv[i] = 3.402823e38f; bestk[i] = 0; }

    // Bs loader: thread t owns code k=t; per chunk loads its 2 float4
    // (d = dc*8 + {0..3} and {4..7}); warp-consecutive k -> conflict-free STS.
    const int lk = tid;                 // 0..255

    const int nkt = Kn / BN;
    for (int kt = 0; kt < nkt; kt++) {
        const int kbase = kt * BN;

        float acc[TM][TN];
        #pragma unroll
        for (int i = 0; i < TM; i++)
            #pragma unroll
            for (int j = 0; j < TN; j++) acc[i][j] = 0.f;

        // prologue: chunk 0 -> buffer 0
        float4 s0 = W4[(size_t)(kbase + lk) * D4 + 0];
        float4 s1 = W4[(size_t)(kbase + lk) * D4 + 1];
        {
            float* B = Bs;
            B[0 * BN + lk] = s0.x; B[1 * BN + lk] = s0.y;
            B[2 * BN + lk] = s0.z; B[3 * BN + lk] = s0.w;
            B[4 * BN + lk] = s1.x; B[5 * BN + lk] = s1.y;
            B[6 * BN + lk] = s1.z; B[7 * BN + lk] = s1.w;
        }
        __syncthreads();

        #pragma unroll 1
        for (int dc = 0; dc < D_DIM / BK; dc++) {
            // issue global loads for next chunk early (L2-resident)
            if (dc < D_DIM / BK - 1) {
                s0 = W4[(size_t)(kbase + lk) * D4 + (dc + 1) * 2 + 0];
                s1 = W4[(size_t)(kbase + lk) * D4 + (dc + 1) * 2 + 1];
            }
            const float* A = As + dc * BK * BM;
            const float* B = Bs + (dc & 1) * (BK * BN);
            #pragma unroll
            for (int dd = 0; dd < BK; dd++) {
                float4 a0 = *(const float4*)&A[dd * BM + rowA0];
                float4 a1 = *(const float4*)&A[dd * BM + rowA1];
                float4 b0 = *(const float4*)&B[dd * BN + colB0];
                float4 b1 = *(const float4*)&B[dd * BN + colB1];
                float ar[8] = {a0.x, a0.y, a0.z, a0.w, a1.x, a1.y, a1.z, a1.w};
                float br[8] = {b0.x, b0.y, b0.z, b0.w, b1.x, b1.y, b1.z, b1.w};
                #pragma unroll
                for (int i = 0; i < TM; i++)
                    #pragma unroll
                    for (int j = 0; j < TN; j++)
                        acc[i][j] = fmaf(ar[i], br[j], acc[i][j]);
            }
            if (dc < D_DIM / BK - 1) {
                float* Bw = Bs + ((dc + 1) & 1) * (BK * BN);
                Bw[0 * BN + lk] = s0.x; Bw[1 * BN + lk] = s0.y;
                Bw[2 * BN + lk] = s0.z; Bw[3 * BN + lk] = s0.w;
                Bw[4 * BN + lk] = s1.x; Bw[5 * BN + lk] = s1.y;
                Bw[6 * BN + lk] = s1.z; Bw[7 * BN + lk] = s1.w;
            }
            __syncthreads();
        }

        // epilogue: score = fl(xsq - 2*dot); ascending k + strict < ties
        #pragma unroll
        for (int j = 0; j < TN; j++) {
            const int kk = kbase + (j < 4 ? colB0 + j : colB1 + j - 4);
            #pragma unroll
            for (int i = 0; i < TM; i++) {
                float sc = xr[i] - 2.0f * acc[i][j];
                if (sc < bestv[i]) { bestv[i] = sc; bestk[i] = kk; }
            }
        }
    }
    // (last dc iteration ended with __syncthreads: all GEMM smem reads done)

    // --- step 1: butterfly reduce over the 8 ng-lanes sharing each row ---
    #pragma unroll
    for (int i = 0; i < TM; i++) {
        float v = bestv[i];
        int   b = bestk[i];
        #pragma unroll
        for (int o = 1; o <= 4; o <<= 1) {
            float v2 = __shfl_xor_sync(0xffffffffu, v, o);
            int   b2 = __shfl_xor_sync(0xffffffffu, b, o);
            if (v2 < v || (v2 == v && b2 < b)) { v = v2; b = b2; }
        }
        if (ng == 0) {
            const int rloc = (i < 4 ? rowA0 + i : rowA1 + i - 4);
            redv[rloc * 4 + wn] = v;
            redk[rloc * 4 + wn] = b;
        }
    }
    __syncthreads();

    // --- step 2: combine the 4 wn-partials per row; gather in teams of 4 ---
    {
        const int r    = tid >> 2;   // 0..63
        const int team = tid & 3;
        float v = redv[r * 4 + 0];
        int   b = redk[r * 4 + 0];
        #pragma unroll
        for (int t = 1; t < 4; t++) {
            float v2 = redv[r * 4 + t];
            int   b2 = redk[r * 4 + t];
            if (v2 < v || (v2 == v && b2 < b)) { v = v2; b = b2; }
        }
        const int row = row0 + r;
        if (write_idx && team == 0) outidx[row] = (float)b;
        const float4* src = W4 + (size_t)b * D4;
        float4*       dst = (float4*)outq + (size_t)row * D4;
        #pragma unroll
        for (int c = 0; c < 16; c++) dst[c * 4 + team] = src[c * 4 + team];
    }
}

// ---------------------------------------------------------------------------
extern "C" void kernel_launch(void* const* d_in, const int* in_sizes, int n_in,
                              void* d_out, int out_size) {
    (void)n_in;
    const float* X = (const float*)d_in[0];
    const float* W = (const float*)d_in[1];
    int nx = in_sizes[0], nw = in_sizes[1];
    if (nx < nw) {
        const float* t = X; X = W; W = t;
        int tt = nx; nx = nw; nw = tt;
    }
    const int Nrows = nx / D_DIM;   // 32768
    const int Kn    = nw / D_DIM;   // 8192

    float* outq = (float*)d_out;
    const int write_idx = (out_size >= Nrows * D_DIM + Nrows) ? 1 : 0;
    float* outidx = write_idx ? ((float*)d_out + (size_t)Nrows * D_DIM) : nullptr;

    const size_t SMEM_BYTES =
        (size_t)(D_DIM * BM + 2 * BK * BN + BM) * sizeof(float);  // 82688
    cudaFuncSetAttribute(vq_kernel, cudaFuncAttributeMaxDynamicSharedMemorySize,
                         (int)SMEM_BYTES);

    vq_kernel<<<Nrows / BM, NTHREADS, SMEM_BYTES>>>(X, W, outq, outidx, Kn, write_idx);
}